// round 3
// baseline (speedup 1.0000x reference)
#include <cuda_runtime.h>
#include <cuda_bf16.h>

#define N_ROWS 16384
#define N_COLS 4096
#define MARGIN 0.1f

#define BLOCKS 512
#define THREADS 256
#define WARPS_TOTAL (BLOCKS * (THREADS / 32))        // 4096
#define ROWS_PER_WARP (N_ROWS / WARPS_TOTAL)         // 4
#define GRAN_PER_ROW (N_COLS / 4)                    // 1024 float4/int4 granules
#define GRAN_PER_LANE (GRAN_PER_ROW / 32)            // 32

// Per-warp partial sums + completion ticket (device globals: no allocation).
__device__ float g_partial[WARPS_TOTAL];
__device__ unsigned int g_count = 0;

__global__ void __launch_bounds__(THREADS) mm_warp_kernel(
    const float* __restrict__ cossim,
    const int* __restrict__ target,
    float* __restrict__ out)
{
    const int t    = threadIdx.x;
    const int lane = t & 31;
    const int wid  = t >> 5;
    const int gw   = blockIdx.x * (THREADS / 32) + wid;   // global warp id

    float acc = 0.0f;   // per-lane accumulator across this warp's rows

#pragma unroll
    for (int r = 0; r < ROWS_PER_WARP; r++) {
        const int row = gw + r * WARPS_TOTAL;
        const float4* __restrict__ crow =
            reinterpret_cast<const float4*>(cossim + (size_t)row * N_COLS);
        const int4* __restrict__ trow =
            reinterpret_cast<const int4*>(target + (size_t)row * N_COLS);

        // ---- Pass 1: scan target, find one-hot column ----
        int jcol = 0;
        bool found = false;
#pragma unroll
        for (int b = 0; b < GRAN_PER_LANE / 8; b++) {   // 4 batches of 8
            int4 v[8];
#pragma unroll
            for (int i = 0; i < 8; i++)
                v[i] = __ldcs(&trow[(b * 8 + i) * 32 + lane]);
#pragma unroll
            for (int i = 0; i < 8; i++) {
                const int g = (b * 8 + i) * 32 + lane;
                if (v[i].x == 1) { jcol = g * 4 + 0; found = true; }
                if (v[i].y == 1) { jcol = g * 4 + 1; found = true; }
                if (v[i].z == 1) { jcol = g * 4 + 2; found = true; }
                if (v[i].w == 1) { jcol = g * 4 + 3; found = true; }
            }
        }

        // Broadcast correct-column cossim value within the warp.
        const unsigned m = __ballot_sync(0xffffffffu, found);
        const int src = __ffs(m) - 1;
        float corr_l = 0.0f;
        if (found)
            corr_l = __ldg(&cossim[(size_t)row * N_COLS + jcol]);
        const float corr = __shfl_sync(0xffffffffu, corr_l, src);

        // ---- Pass 2: stream cossim, accumulate hinge ----
        // (correct column contributes exactly MARGIN; removed once per row at end)
        float sum = 0.0f;
#pragma unroll
        for (int b = 0; b < GRAN_PER_LANE / 8; b++) {
            float4 c[8];
#pragma unroll
            for (int i = 0; i < 8; i++)
                c[i] = __ldcs(&crow[(b * 8 + i) * 32 + lane]);
#pragma unroll
            for (int i = 0; i < 8; i++) {
                sum += fmaxf(MARGIN + c[i].x - corr, 0.0f);
                sum += fmaxf(MARGIN + c[i].y - corr, 0.0f);
                sum += fmaxf(MARGIN + c[i].z - corr, 0.0f);
                sum += fmaxf(MARGIN + c[i].w - corr, 0.0f);
            }
        }
        acc += sum;
    }

    // Warp reduce acc, lane 0 publishes the warp partial.
#pragma unroll
    for (int off = 16; off > 0; off >>= 1)
        acc += __shfl_down_sync(0xffffffffu, acc, off);
    if (lane == 0)
        g_partial[gw] = acc - (float)ROWS_PER_WARP * MARGIN;

    // ---- Last CTA performs the final deterministic reduction ----
    __shared__ unsigned int s_ticket;
    __shared__ float s_warp[THREADS / 32];
    __syncthreads();
    if (t == 0) {
        __threadfence();                      // publish partials before ticket
        s_ticket = atomicAdd(&g_count, 1u);
    }
    __syncthreads();

    if (s_ticket == (unsigned int)(BLOCKS - 1)) {
        __threadfence();                      // acquire: see all g_partial

        const float4* __restrict__ p4 = reinterpret_cast<const float4*>(g_partial);
        float s = 0.0f;
#pragma unroll
        for (int k = 0; k < WARPS_TOTAL / 4 / THREADS; k++) {   // 4 granules/thread
            float4 v = __ldcg(&p4[k * THREADS + t]);
            s += v.x + v.y + v.z + v.w;
        }

#pragma unroll
        for (int off = 16; off > 0; off >>= 1)
            s += __shfl_down_sync(0xffffffffu, s, off);
        if (lane == 0) s_warp[wid] = s;
        __syncthreads();

        if (t == 0) {
            float v = s_warp[0];
#pragma unroll
            for (int w = 1; w < THREADS / 32; w++) v += s_warp[w];
            out[0] = v * (1.0f / (float)N_ROWS);
            g_count = 0;                      // reset for next graph replay
        }
    }
}

extern "C" void kernel_launch(void* const* d_in, const int* in_sizes, int n_in,
                              void* d_out, int out_size)
{
    const float* cossim = (const float*)d_in[0];
    const int*   target = (const int*)d_in[1];
    float* out = (float*)d_out;

    mm_warp_kernel<<<BLOCKS, THREADS>>>(cossim, target, out);
}

// round 4
// speedup vs baseline: 1.0155x; 1.0155x over previous
#include <cuda_runtime.h>
#include <cuda_bf16.h>

#define N_ROWS 16384
#define N_COLS 4096
#define MARGIN 0.1f
#define THREADS 256

// Scratch (device globals: no allocation).
__device__ float g_corr[N_ROWS];          // correct-class cossim per row
__device__ float g_partial[N_ROWS];       // per-row hinge partial
__device__ unsigned int g_count = 0;      // completion ticket

// ---------------- Kernel A: scan target, capture correct-class value ----------------
// Block per row; 256 threads x 4 int4 = 4096 cols. No barriers, no reductions.
__global__ void __launch_bounds__(THREADS) mm_scan_kernel(
    const float* __restrict__ cossim,
    const int* __restrict__ target)
{
    const int row = blockIdx.x;
    const int t = threadIdx.x;
    const int4* __restrict__ trow =
        reinterpret_cast<const int4*>(target + (size_t)row * N_COLS);

    int4 v[4];
#pragma unroll
    for (int k = 0; k < 4; k++)
        v[k] = __ldcs(&trow[k * THREADS + t]);

    int col = -1;
#pragma unroll
    for (int k = 0; k < 4; k++) {
        const int g = (k * THREADS + t) * 4;
        if (v[k].x == 1) col = g + 0;
        if (v[k].y == 1) col = g + 1;
        if (v[k].z == 1) col = g + 2;
        if (v[k].w == 1) col = g + 3;
    }

    if (col >= 0)   // exactly one thread per row
        g_corr[row] = __ldg(&cossim[(size_t)row * N_COLS + col]);
}

// ---------------- Kernel B: stream cossim, hinge sum, fused final reduce ----------------
__global__ void __launch_bounds__(THREADS) mm_hinge_kernel(
    const float* __restrict__ cossim,
    float* __restrict__ out)
{
    const int row = blockIdx.x;
    const int t = threadIdx.x;
    const int lane = t & 31;
    const int wid  = t >> 5;

    __shared__ float s_warp[THREADS / 32];
    __shared__ unsigned int s_ticket;

    // Uniform per-block scalar; issue first (L2-resident from kernel A).
    const float corr = __ldg(&g_corr[row]);

    const float4* __restrict__ crow =
        reinterpret_cast<const float4*>(cossim + (size_t)row * N_COLS);

    float4 c[4];
#pragma unroll
    for (int k = 0; k < 4; k++)
        c[k] = __ldcs(&crow[k * THREADS + t]);

    // Hinge sum (correct column contributes exactly MARGIN; removed at write).
    float sum = 0.0f;
#pragma unroll
    for (int k = 0; k < 4; k++) {
        sum += fmaxf(MARGIN + c[k].x - corr, 0.0f);
        sum += fmaxf(MARGIN + c[k].y - corr, 0.0f);
        sum += fmaxf(MARGIN + c[k].z - corr, 0.0f);
        sum += fmaxf(MARGIN + c[k].w - corr, 0.0f);
    }

    // Block reduce (8 warps, one sync).
#pragma unroll
    for (int off = 16; off > 0; off >>= 1)
        sum += __shfl_down_sync(0xffffffffu, sum, off);
    if (lane == 0) s_warp[wid] = sum;
    __syncthreads();

    if (t == 0) {
        float v = s_warp[0];
#pragma unroll
        for (int w = 1; w < THREADS / 32; w++) v += s_warp[w];
        g_partial[row] = v - MARGIN;
        __threadfence();
        s_ticket = atomicAdd(&g_count, 1u);
    }
    __syncthreads();

    // Last CTA: deterministic final reduction of 16384 partials.
    if (s_ticket == (unsigned int)(N_ROWS - 1)) {
        __threadfence();

        const float4* __restrict__ p4 = reinterpret_cast<const float4*>(g_partial);
        float s = 0.0f;
#pragma unroll
        for (int k = 0; k < (N_ROWS / 4) / THREADS; k++) {   // 16 granules/thread
            float4 v = __ldcg(&p4[k * THREADS + t]);
            s += v.x + v.y + v.z + v.w;
        }

#pragma unroll
        for (int off = 16; off > 0; off >>= 1)
            s += __shfl_down_sync(0xffffffffu, s, off);
        if (lane == 0) s_warp[wid] = s;
        __syncthreads();

        if (t == 0) {
            float v = s_warp[0];
#pragma unroll
            for (int w = 1; w < THREADS / 32; w++) v += s_warp[w];
            out[0] = v * (1.0f / (float)N_ROWS);
            g_count = 0;   // reset for graph replay
        }
    }
}

extern "C" void kernel_launch(void* const* d_in, const int* in_sizes, int n_in,
                              void* d_out, int out_size)
{
    const float* cossim = (const float*)d_in[0];
    const int*   target = (const int*)d_in[1];
    float* out = (float*)d_out;

    mm_scan_kernel<<<N_ROWS, THREADS>>>(cossim, target);
    mm_hinge_kernel<<<N_ROWS, THREADS>>>(cossim, out);
}

// round 5
// speedup vs baseline: 1.0662x; 1.0499x over previous
#include <cuda_runtime.h>
#include <cuda_bf16.h>

#define N_ROWS 16384
#define N_COLS 4096
#define MARGIN 0.1f
#define THREADS 512
#define NWARP (THREADS / 32)

// Scratch (device globals: no allocation).
__device__ float g_partial[N_ROWS];
__device__ unsigned int g_count = 0;

// One block = one row. 512 threads * 8 elems = 4096 columns.
// Last CTA to finish reduces all row partials and writes the scalar loss.
__global__ void __launch_bounds__(THREADS) mm_fused_kernel(
    const float* __restrict__ cossim,
    const int* __restrict__ target,
    float* __restrict__ out)
{
    const int row = blockIdx.x;
    const int t = threadIdx.x;
    const int lane = t & 31;
    const int wid  = t >> 5;

    const float4* __restrict__ crow =
        reinterpret_cast<const float4*>(cossim + (size_t)row * N_COLS);
    const int4* __restrict__ trow =
        reinterpret_cast<const int4*>(target + (size_t)row * N_COLS);

    __shared__ float s_corr;
    __shared__ float s_warp[NWARP];
    __shared__ unsigned int s_ticket;

    // ---- Front-batched streaming loads: 2x float4 + 2x int4 per thread ----
    float4 c0 = __ldcs(&crow[t]);
    float4 c1 = __ldcs(&crow[THREADS + t]);
    int4   t0 = __ldcs(&trow[t]);
    int4   t1 = __ldcs(&trow[THREADS + t]);

    // Exactly one thread in the block holds the one-hot column.
    float corr_local = 0.0f;
    bool found = false;
    if (t0.x == 1) { corr_local = c0.x; found = true; }
    if (t0.y == 1) { corr_local = c0.y; found = true; }
    if (t0.z == 1) { corr_local = c0.z; found = true; }
    if (t0.w == 1) { corr_local = c0.w; found = true; }
    if (t1.x == 1) { corr_local = c1.x; found = true; }
    if (t1.y == 1) { corr_local = c1.y; found = true; }
    if (t1.z == 1) { corr_local = c1.z; found = true; }
    if (t1.w == 1) { corr_local = c1.w; found = true; }

    if (found) s_corr = corr_local;
    __syncthreads();
    const float corr = s_corr;

    // Hinge sum over this thread's 8 elements (correct column contributes
    // exactly MARGIN; removed once per row at the write).
    float sum = 0.0f;
    sum += fmaxf(MARGIN + c0.x - corr, 0.0f);
    sum += fmaxf(MARGIN + c0.y - corr, 0.0f);
    sum += fmaxf(MARGIN + c0.z - corr, 0.0f);
    sum += fmaxf(MARGIN + c0.w - corr, 0.0f);
    sum += fmaxf(MARGIN + c1.x - corr, 0.0f);
    sum += fmaxf(MARGIN + c1.y - corr, 0.0f);
    sum += fmaxf(MARGIN + c1.z - corr, 0.0f);
    sum += fmaxf(MARGIN + c1.w - corr, 0.0f);

    // Block reduce (16 warps).
#pragma unroll
    for (int off = 16; off > 0; off >>= 1)
        sum += __shfl_down_sync(0xffffffffu, sum, off);
    if (lane == 0) s_warp[wid] = sum;
    __syncthreads();

    if (t == 0) {
        float v = s_warp[0];
#pragma unroll
        for (int w = 1; w < NWARP; w++) v += s_warp[w];
        g_partial[row] = v - MARGIN;           // remove correct-column hinge
        __threadfence();                        // publish before ticket
        s_ticket = atomicAdd(&g_count, 1u);
    }
    __syncthreads();

    // ---- Last CTA performs the final deterministic reduction ----
    if (s_ticket == (unsigned int)(N_ROWS - 1)) {
        __threadfence();  // acquire: see all g_partial writes

        const float4* __restrict__ p4 = reinterpret_cast<const float4*>(g_partial);
        float s = 0.0f;
#pragma unroll
        for (int k = 0; k < (N_ROWS / 4) / THREADS; k++) {   // 8 granules/thread
            float4 v = __ldcg(&p4[k * THREADS + t]);
            s += v.x + v.y + v.z + v.w;
        }

#pragma unroll
        for (int off = 16; off > 0; off >>= 1)
            s += __shfl_down_sync(0xffffffffu, s, off);
        if (lane == 0) s_warp[wid] = s;
        __syncthreads();

        if (t == 0) {
            float v = s_warp[0];
#pragma unroll
            for (int w = 1; w < NWARP; w++) v += s_warp[w];
            out[0] = v * (1.0f / (float)N_ROWS);
            g_count = 0;                        // reset for next graph replay
        }
    }
}

extern "C" void kernel_launch(void* const* d_in, const int* in_sizes, int n_in,
                              void* d_out, int out_size)
{
    const float* cossim = (const float*)d_in[0];
    const int*   target = (const int*)d_in[1];
    float* out = (float*)d_out;

    mm_fused_kernel<<<N_ROWS, THREADS>>>(cossim, target, out);
}

// round 6
// speedup vs baseline: 1.0972x; 1.0291x over previous
#include <cuda_runtime.h>
#include <cuda_bf16.h>

#define N_ROWS 16384
#define N_COLS 4096
#define MARGIN 0.1f
#define THREADS 256
#define GRID 512
#define ROWS_PER_CTA (N_ROWS / GRID)   // 32, exact
#define NWARP (THREADS / 32)

// Scratch (device globals: no allocation).
__device__ float g_partial[GRID];
__device__ unsigned int g_count = 0;

__global__ void __launch_bounds__(THREADS, 4) mm_pipe_kernel(
    const float* __restrict__ cossim,
    const int* __restrict__ target,
    float* __restrict__ out)
{
    const int bid  = blockIdx.x;
    const int t    = threadIdx.x;
    const int lane = t & 31;
    const int wid  = t >> 5;

    __shared__ float s_corr[2];
    __shared__ float s_warp[NWARP];
    __shared__ unsigned int s_ticket;

    // ---- Preload first row (row = bid) ----
    float4 c[4];
    int4   tv[4];
    {
        const float4* __restrict__ crow =
            reinterpret_cast<const float4*>(cossim + (size_t)bid * N_COLS);
        const int4* __restrict__ trow =
            reinterpret_cast<const int4*>(target + (size_t)bid * N_COLS);
#pragma unroll
        for (int k = 0; k < 4; k++) c[k]  = crow[k * THREADS + t];
#pragma unroll
        for (int k = 0; k < 4; k++) tv[k] = trow[k * THREADS + t];
    }

    float acc = 0.0f;
    int par = 0;

#pragma unroll 1
    for (int r = bid; r < N_ROWS; r += GRID, par ^= 1) {
        // ---- 1) Scan current target regs (ALU only; tv dies here) ----
        float corr_local = 0.0f;
        bool found = false;
#pragma unroll
        for (int k = 0; k < 4; k++) {
            if (tv[k].x == 1) { corr_local = c[k].x; found = true; }
            if (tv[k].y == 1) { corr_local = c[k].y; found = true; }
            if (tv[k].z == 1) { corr_local = c[k].z; found = true; }
            if (tv[k].w == 1) { corr_local = c[k].w; found = true; }
        }

        // ---- 2) Issue NEXT row's loads (in flight across barrier+compute) ----
        float4 cn[4];
        int4   tn[4];
        const int rn = r + GRID;
        if (rn < N_ROWS) {
            const float4* __restrict__ crow =
                reinterpret_cast<const float4*>(cossim + (size_t)rn * N_COLS);
            const int4* __restrict__ trow =
                reinterpret_cast<const int4*>(target + (size_t)rn * N_COLS);
#pragma unroll
            for (int k = 0; k < 4; k++) cn[k] = crow[k * THREADS + t];
#pragma unroll
            for (int k = 0; k < 4; k++) tn[k] = trow[k * THREADS + t];
        }

        // ---- 3) Broadcast corr (parity double-buffered, one barrier) ----
        if (found) s_corr[par] = corr_local;
        __syncthreads();
        const float corr = s_corr[par];

        // ---- 4) Hinge on current row's register-held cossim ----
        // (correct column contributes exactly MARGIN; removed per-CTA at end)
        float sum = 0.0f;
#pragma unroll
        for (int k = 0; k < 4; k++) {
            sum += fmaxf(MARGIN + c[k].x - corr, 0.0f);
            sum += fmaxf(MARGIN + c[k].y - corr, 0.0f);
            sum += fmaxf(MARGIN + c[k].z - corr, 0.0f);
            sum += fmaxf(MARGIN + c[k].w - corr, 0.0f);
        }
        acc += sum;

        // ---- 5) Rotate pipeline ----
#pragma unroll
        for (int k = 0; k < 4; k++) { c[k] = cn[k]; tv[k] = tn[k]; }
    }

    // ---- Block reduce per-CTA accumulator ----
#pragma unroll
    for (int off = 16; off > 0; off >>= 1)
        acc += __shfl_down_sync(0xffffffffu, acc, off);
    if (lane == 0) s_warp[wid] = acc;
    __syncthreads();

    if (t == 0) {
        float v = s_warp[0];
#pragma unroll
        for (int w = 1; w < NWARP; w++) v += s_warp[w];
        g_partial[bid] = v - (float)ROWS_PER_CTA * MARGIN;
        __threadfence();
        s_ticket = atomicAdd(&g_count, 1u);
    }
    __syncthreads();

    // ---- Last CTA: deterministic final reduction of 512 partials ----
    if (s_ticket == (unsigned int)(GRID - 1)) {
        __threadfence();

        float s = __ldcg(&g_partial[t]) + __ldcg(&g_partial[THREADS + t]);

#pragma unroll
        for (int off = 16; off > 0; off >>= 1)
            s += __shfl_down_sync(0xffffffffu, s, off);
        if (lane == 0) s_warp[wid] = s;
        __syncthreads();

        if (t == 0) {
            float v = s_warp[0];
#pragma unroll
            for (int w = 1; w < NWARP; w++) v += s_warp[w];
            out[0] = v * (1.0f / (float)N_ROWS);
            g_count = 0;   // reset for next graph replay
        }
    }
}

extern "C" void kernel_launch(void* const* d_in, const int* in_sizes, int n_in,
                              void* d_out, int out_size)
{
    const float* cossim = (const float*)d_in[0];
    const int*   target = (const int*)d_in[1];
    float* out = (float*)d_out;

    mm_pipe_kernel<<<GRID, THREADS>>>(cossim, target, out);
}